// round 10
// baseline (speedup 1.0000x reference)
#include <cuda_runtime.h>
#include <stdint.h>

#define N_NODES 100000
#define N_EDGES 600000
#define D 128
#define H 256
#define TILE_M 128
#define NTILES ((N_NODES + TILE_M - 1) / TILE_M)   // 782

#define LDX 132   // smem row stride (floats) for 128-col tile (mod 32 == 4 -> conflict-free frags)
#define LDH 260   // smem row stride (floats) for 256-col tile

// Scratch (allocation-free rule: device globals)
__device__ float g_m[(size_t)N_NODES * D];
__device__ float g_agg[(size_t)N_NODES * D];

// Pre-packed tf32 weights in mma-fragment order:
//   pW[(kt*Ng + g)*32 + lane] = { tf32(W[kt*8   + lane%4][g*8 + lane/4]),
//                                 tf32(W[kt*8+4 + lane%4][g*8 + lane/4]) }
__device__ uint2 g_pWm1[16 * 32 * 32];   // Wm1: K=128 -> KT=16, N=256 -> NG=32
__device__ uint2 g_pWm2[32 * 16 * 32];   // Wm2: K=256 -> KT=32, N=128 -> NG=16
__device__ uint2 g_pWn1[32 * 32 * 32];   // Wn1: K=256 -> KT=32, N=256 -> NG=32
__device__ uint2 g_pWn2[32 * 16 * 32];   // Wn2: K=256 -> KT=32, N=128 -> NG=16

// ---------------------------------------------------------------------------
// helpers
// ---------------------------------------------------------------------------
__device__ __forceinline__ uint32_t f2tf(float f) {
    uint32_t u;
    asm("cvt.rna.tf32.f32 %0, %1;" : "=r"(u) : "f"(f));
    return u;
}

__device__ __forceinline__ void mma_tf32(float c[4], const uint32_t a[4], const uint32_t* b) {
    asm volatile(
        "mma.sync.aligned.m16n8k8.row.col.f32.tf32.tf32.f32 "
        "{%0,%1,%2,%3}, {%4,%5,%6,%7}, {%8,%9}, {%0,%1,%2,%3};\n"
        : "+f"(c[0]), "+f"(c[1]), "+f"(c[2]), "+f"(c[3])
        : "r"(a[0]), "r"(a[1]), "r"(a[2]), "r"(a[3]),
          "r"(b[0]), "r"(b[1]));
}

// ---------------------------------------------------------------------------
// One fused pack kernel: all four weight matrices -> fragment-ordered tf32
// ---------------------------------------------------------------------------
__device__ __forceinline__ void pack_one(const float* __restrict__ W,
                                         uint2* __restrict__ pW,
                                         int id, int Ng, int N)
{
    int lane = id & 31;
    int g    = (id >> 5) % Ng;
    int kt   = (id >> 5) / Ng;
    int lr = lane & 3, lq = lane >> 2;
    int col = g * 8 + lq;
    uint2 v;
    v.x = f2tf(W[(size_t)(kt * 8 + lr)     * N + col]);
    v.y = f2tf(W[(size_t)(kt * 8 + 4 + lr) * N + col]);
    pW[id] = v;
}

__global__ void pack_all_kernel(const float* __restrict__ Wm1, const float* __restrict__ Wm2,
                                const float* __restrict__ Wn1, const float* __restrict__ Wn2)
{
    const int n1 = 16 * 32 * 32;   // pWm1
    const int n2 = 32 * 16 * 32;   // pWm2
    const int n3 = 32 * 32 * 32;   // pWn1
    const int n4 = 32 * 16 * 32;   // pWn2
    int id = blockIdx.x * 256 + threadIdx.x;
    if (id < n1)                     pack_one(Wm1, g_pWm1, id,               32, H);
    else if (id < n1 + n2)           pack_one(Wm2, g_pWm2, id - n1,          16, D);
    else if (id < n1 + n2 + n3)      pack_one(Wn1, g_pWn1, id - n1 - n2,     32, H);
    else if (id < n1 + n2 + n3 + n4) pack_one(Wn2, g_pWn2, id - n1 - n2 - n3, 16, D);
}

// ---------------------------------------------------------------------------
// Kernel 1: m = relu(X @ Wm1 + bm1) @ Wm2 + bm2   + zero g_agg rows
//   256 threads (8 warps).
//   GEMM1: warp grid 2x4, warp tile 64x64  (rt=4, ct=8)
//   GEMM2: warp grid 4x2, warp tile 32x64  (rt=2, ct=8)
// ---------------------------------------------------------------------------
__global__ __launch_bounds__(256, 1)
void msg_mlp_kernel(const float* __restrict__ nodes,
                    const float* __restrict__ bm1, const float* __restrict__ bm2)
{
    extern __shared__ uint32_t smem[];
    uint32_t* sX = smem;                    // [128][LDX]
    uint32_t* sH = smem + TILE_M * LDX;     // [128][LDH]

    const int row0 = blockIdx.x * TILE_M;
    const int tid  = threadIdx.x;
    const int warp = tid >> 5;
    const int lane = tid & 31;
    const int lq   = lane >> 2;
    const int lr   = lane & 3;

    // zero this tile's g_agg rows (independent of GEMMs)
    for (int i = tid; i < TILE_M * (D / 4); i += 256) {
        int r  = i >> 5;
        int c4 = (i & 31) * 4;
        int gr = row0 + r;
        if (gr < N_NODES)
            *reinterpret_cast<float4*>(g_agg + (size_t)gr * D + c4) =
                make_float4(0.f, 0.f, 0.f, 0.f);
    }

    // stage X tile (fp32 -> tf32), STS.128 conflict-free
    for (int i = tid; i < TILE_M * (D / 4); i += 256) {
        int r  = i >> 5;
        int c4 = (i & 31) * 4;
        float4 v = make_float4(0.f, 0.f, 0.f, 0.f);
        int gr = row0 + r;
        if (gr < N_NODES) v = *reinterpret_cast<const float4*>(nodes + (size_t)gr * D + c4);
        uint32_t* dst = sX + r * LDX + c4;
        dst[0] = f2tf(v.x); dst[1] = f2tf(v.y); dst[2] = f2tf(v.z); dst[3] = f2tf(v.w);
    }
    __syncthreads();

    // ---- GEMM1: hidden[128x256] = relu(X @ Wm1 + bm1)
    {
        const int wr = warp >> 2;           // 0..1 -> rows wr*64
        const int wc = warp & 3;            // 0..3 -> cols wc*64
        const int g0 = wc * 8;
        const int KT = D / 8;               // 16
        const int NG = H / 8;               // 32

        float acc[4][8][4];
        #pragma unroll
        for (int i = 0; i < 4; ++i)
            #pragma unroll
            for (int j = 0; j < 8; ++j)
                #pragma unroll
                for (int k = 0; k < 4; ++k) acc[i][j][k] = 0.f;

        uint2 bb[2][8];
        #pragma unroll
        for (int ct = 0; ct < 8; ++ct)
            bb[0][ct] = g_pWm1[(size_t)(g0 + ct) * 32 + lane];

        #pragma unroll 1
        for (int kt = 0; kt < KT; ++kt) {
            const int cur = kt & 1;
            if (kt + 1 < KT) {
                #pragma unroll
                for (int ct = 0; ct < 8; ++ct)
                    bb[cur ^ 1][ct] = g_pWm1[(size_t)((kt + 1) * NG + g0 + ct) * 32 + lane];
            }
            const int kb = kt * 8;
            uint32_t a[4], an[4];
            {
                const uint32_t* b0 = sX + (wr * 64 + lq) * LDX + kb + lr;
                a[0] = b0[0]; a[1] = b0[8 * LDX]; a[2] = b0[4]; a[3] = b0[8 * LDX + 4];
            }
            #pragma unroll
            for (int rt = 0; rt < 4; ++rt) {
                if (rt < 3) {
                    const uint32_t* bn = sX + (wr * 64 + (rt + 1) * 16 + lq) * LDX + kb + lr;
                    an[0] = bn[0]; an[1] = bn[8 * LDX]; an[2] = bn[4]; an[3] = bn[8 * LDX + 4];
                }
                #pragma unroll
                for (int ct = 0; ct < 8; ++ct)
                    mma_tf32(acc[rt][ct], a, reinterpret_cast<const uint32_t*>(&bb[cur][ct]));
                if (rt < 3) { a[0] = an[0]; a[1] = an[1]; a[2] = an[2]; a[3] = an[3]; }
            }
        }
        // bias + relu -> sH (tf32)
        #pragma unroll
        for (int rt = 0; rt < 4; ++rt) {
            #pragma unroll
            for (int ct = 0; ct < 8; ++ct) {
                int r = wr * 64 + rt * 16 + lq;
                int c = wc * 64 + ct * 8 + lr * 2;
                float b0 = __ldg(bm1 + c), b1 = __ldg(bm1 + c + 1);
                sH[r * LDH + c]           = f2tf(fmaxf(acc[rt][ct][0] + b0, 0.f));
                sH[r * LDH + c + 1]       = f2tf(fmaxf(acc[rt][ct][1] + b1, 0.f));
                sH[(r + 8) * LDH + c]     = f2tf(fmaxf(acc[rt][ct][2] + b0, 0.f));
                sH[(r + 8) * LDH + c + 1] = f2tf(fmaxf(acc[rt][ct][3] + b1, 0.f));
            }
        }
    }
    __syncthreads();

    // ---- GEMM2: m[128x128] = hidden @ Wm2 + bm2
    {
        const int wr = warp >> 1;           // 0..3 -> rows wr*32
        const int wc = warp & 1;            // 0..1 -> cols wc*64
        const int g0 = wc * 8;
        const int KT = H / 8;               // 32
        const int NG = D / 8;               // 16

        float acc[2][8][4];
        #pragma unroll
        for (int i = 0; i < 2; ++i)
            #pragma unroll
            for (int j = 0; j < 8; ++j)
                #pragma unroll
                for (int k = 0; k < 4; ++k) acc[i][j][k] = 0.f;

        uint2 bb[2][8];
        #pragma unroll
        for (int ct = 0; ct < 8; ++ct)
            bb[0][ct] = g_pWm2[(size_t)(g0 + ct) * 32 + lane];

        #pragma unroll 1
        for (int kt = 0; kt < KT; ++kt) {
            const int cur = kt & 1;
            if (kt + 1 < KT) {
                #pragma unroll
                for (int ct = 0; ct < 8; ++ct)
                    bb[cur ^ 1][ct] = g_pWm2[(size_t)((kt + 1) * NG + g0 + ct) * 32 + lane];
            }
            const int kb = kt * 8;
            uint32_t a[4], an[4];
            {
                const uint32_t* b0 = sH + (wr * 32 + lq) * LDH + kb + lr;
                a[0] = b0[0]; a[1] = b0[8 * LDH]; a[2] = b0[4]; a[3] = b0[8 * LDH + 4];
            }
            #pragma unroll
            for (int rt = 0; rt < 2; ++rt) {
                if (rt < 1) {
                    const uint32_t* bn = sH + (wr * 32 + 16 + lq) * LDH + kb + lr;
                    an[0] = bn[0]; an[1] = bn[8 * LDH]; an[2] = bn[4]; an[3] = bn[8 * LDH + 4];
                }
                #pragma unroll
                for (int ct = 0; ct < 8; ++ct)
                    mma_tf32(acc[rt][ct], a, reinterpret_cast<const uint32_t*>(&bb[cur][ct]));
                if (rt < 1) { a[0] = an[0]; a[1] = an[1]; a[2] = an[2]; a[3] = an[3]; }
            }
        }
        #pragma unroll
        for (int rt = 0; rt < 2; ++rt) {
            #pragma unroll
            for (int ct = 0; ct < 8; ++ct) {
                int r = wr * 32 + rt * 16 + lq;
                int c = wc * 64 + ct * 8 + lr * 2;
                float b0 = __ldg(bm2 + c), b1 = __ldg(bm2 + c + 1);
                int gr = row0 + r;
                if (gr < N_NODES) {
                    float2 v = make_float2(acc[rt][ct][0] + b0, acc[rt][ct][1] + b1);
                    *reinterpret_cast<float2*>(g_m + (size_t)gr * D + c) = v;
                }
                int gr2 = gr + 8;
                if (gr2 < N_NODES) {
                    float2 v = make_float2(acc[rt][ct][2] + b0, acc[rt][ct][3] + b1);
                    *reinterpret_cast<float2*>(g_m + (size_t)gr2 * D + c) = v;
                }
            }
        }
    }
}

// ---------------------------------------------------------------------------
// Kernel 2: agg[recv] += m[send]   (one warp per edge, vector red to L2)
// ---------------------------------------------------------------------------
__global__ __launch_bounds__(256)
void scatter_kernel(const int* __restrict__ senders, const int* __restrict__ receivers)
{
    int e = (blockIdx.x * 256 + threadIdx.x) >> 5;
    int lane = threadIdx.x & 31;
    if (e >= N_EDGES) return;
    int s = __ldg(senders + e);
    int r = __ldg(receivers + e);
    float4 v = *reinterpret_cast<const float4*>(g_m + (size_t)s * D + lane * 4);
    float* dst = g_agg + (size_t)r * D + lane * 4;
    asm volatile("red.global.add.v4.f32 [%0], {%1,%2,%3,%4};"
                 :: "l"(dst), "f"(v.x), "f"(v.y), "f"(v.z), "f"(v.w)
                 : "memory");
}

// ---------------------------------------------------------------------------
// Kernel 3: out = nodes + relu([nodes||agg] @ Wn1 + bn1) @ Wn2 + bn2
//   256 threads. GEMM1: 2x4 grid, 64x64 tiles. GEMM2: 4x2 grid, 32x64 tiles.
// ---------------------------------------------------------------------------
__global__ __launch_bounds__(256, 1)
void node_mlp_kernel(const float* __restrict__ nodes,
                     const float* __restrict__ bn1, const float* __restrict__ bn2,
                     float* __restrict__ out)
{
    extern __shared__ uint32_t smem[];
    uint32_t* sA = smem;   // [128][LDH]; A = [X||agg], later reused as hidden

    const int row0 = blockIdx.x * TILE_M;
    const int tid  = threadIdx.x;
    const int warp = tid >> 5;
    const int lane = tid & 31;
    const int lq   = lane >> 2;
    const int lr   = lane & 3;

    // stage A = [nodes || agg], 128 x 256, tf32
    for (int i = tid; i < TILE_M * (2 * D / 4); i += 256) {
        int r  = i >> 6;
        int c4 = (i & 63) * 4;
        float4 v = make_float4(0.f, 0.f, 0.f, 0.f);
        int gr = row0 + r;
        if (gr < N_NODES) {
            if (c4 < D) v = *reinterpret_cast<const float4*>(nodes + (size_t)gr * D + c4);
            else        v = *reinterpret_cast<const float4*>(g_agg + (size_t)gr * D + (c4 - D));
        }
        uint32_t* dst = sA + r * LDH + c4;
        dst[0] = f2tf(v.x); dst[1] = f2tf(v.y); dst[2] = f2tf(v.z); dst[3] = f2tf(v.w);
    }
    __syncthreads();

    // ---- GEMM1: hidden[128x256] = relu(A @ Wn1 + bn1)
    const int wr1 = warp >> 2;              // 0..1
    const int wc1 = warp & 3;               // 0..3
    float acc1[4][8][4];
    #pragma unroll
    for (int i = 0; i < 4; ++i)
        #pragma unroll
        for (int j = 0; j < 8; ++j)
            #pragma unroll
            for (int k = 0; k < 4; ++k) acc1[i][j][k] = 0.f;

    {
        const int g0 = wc1 * 8;
        const int KT = (2 * D) / 8;         // 32
        const int NG = H / 8;               // 32

        uint2 bb[2][8];
        #pragma unroll
        for (int ct = 0; ct < 8; ++ct)
            bb[0][ct] = g_pWn1[(size_t)(g0 + ct) * 32 + lane];

        #pragma unroll 1
        for (int kt = 0; kt < KT; ++kt) {
            const int cur = kt & 1;
            if (kt + 1 < KT) {
                #pragma unroll
                for (int ct = 0; ct < 8; ++ct)
                    bb[cur ^ 1][ct] = g_pWn1[(size_t)((kt + 1) * NG + g0 + ct) * 32 + lane];
            }
            const int kb = kt * 8;
            uint32_t a[4], an[4];
            {
                const uint32_t* b0 = sA + (wr1 * 64 + lq) * LDH + kb + lr;
                a[0] = b0[0]; a[1] = b0[8 * LDH]; a[2] = b0[4]; a[3] = b0[8 * LDH + 4];
            }
            #pragma unroll
            for (int rt = 0; rt < 4; ++rt) {
                if (rt < 3) {
                    const uint32_t* bn = sA + (wr1 * 64 + (rt + 1) * 16 + lq) * LDH + kb + lr;
                    an[0] = bn[0]; an[1] = bn[8 * LDH]; an[2] = bn[4]; an[3] = bn[8 * LDH + 4];
                }
                #pragma unroll
                for (int ct = 0; ct < 8; ++ct)
                    mma_tf32(acc1[rt][ct], a, reinterpret_cast<const uint32_t*>(&bb[cur][ct]));
                if (rt < 3) { a[0] = an[0]; a[1] = an[1]; a[2] = an[2]; a[3] = an[3]; }
            }
        }
    }
    __syncthreads();   // all warps done READING sA

    // write hidden (bias + relu, tf32) over sA
    #pragma unroll
    for (int rt = 0; rt < 4; ++rt) {
        #pragma unroll
        for (int ct = 0; ct < 8; ++ct) {
            int r = wr1 * 64 + rt * 16 + lq;
            int c = wc1 * 64 + ct * 8 + lr * 2;
            float b0 = __ldg(bn1 + c), b1 = __ldg(bn1 + c + 1);
            sA[r * LDH + c]           = f2tf(fmaxf(acc1[rt][ct][0] + b0, 0.f));
            sA[r * LDH + c + 1]       = f2tf(fmaxf(acc1[rt][ct][1] + b1, 0.f));
            sA[(r + 8) * LDH + c]     = f2tf(fmaxf(acc1[rt][ct][2] + b0, 0.f));
            sA[(r + 8) * LDH + c + 1] = f2tf(fmaxf(acc1[rt][ct][3] + b1, 0.f));
        }
    }
    __syncthreads();

    // ---- GEMM2: out = nodes + hidden @ Wn2 + bn2
    {
        const int wr = warp >> 1;           // 0..3
        const int wc = warp & 1;            // 0..1
        const int g0 = wc * 8;
        const int KT = H / 8;               // 32
        const int NG = D / 8;               // 16

        float acc[2][8][4];
        #pragma unroll
        for (int i = 0; i < 2; ++i)
            #pragma unroll
            for (int j = 0; j < 8; ++j)
                #pragma unroll
                for (int k = 0; k < 4; ++k) acc[i][j][k] = 0.f;

        uint2 bb[2][8];
        #pragma unroll
        for (int ct = 0; ct < 8; ++ct)
            bb[0][ct] = g_pWn2[(size_t)(g0 + ct) * 32 + lane];

        #pragma unroll 1
        for (int kt = 0; kt < KT; ++kt) {
            const int cur = kt & 1;
            if (kt + 1 < KT) {
                #pragma unroll
                for (int ct = 0; ct < 8; ++ct)
                    bb[cur ^ 1][ct] = g_pWn2[(size_t)((kt + 1) * NG + g0 + ct) * 32 + lane];
            }
            const int kb = kt * 8;
            uint32_t a[4], an[4];
            {
                const uint32_t* b0 = sA + (wr * 32 + lq) * LDH + kb + lr;
                a[0] = b0[0]; a[1] = b0[8 * LDH]; a[2] = b0[4]; a[3] = b0[8 * LDH + 4];
            }
            #pragma unroll
            for (int rt = 0; rt < 2; ++rt) {
                if (rt < 1) {
                    const uint32_t* bn = sA + (wr * 32 + 16 + lq) * LDH + kb + lr;
                    an[0] = bn[0]; an[1] = bn[8 * LDH]; an[2] = bn[4]; an[3] = bn[8 * LDH + 4];
                }
                #pragma unroll
                for (int ct = 0; ct < 8; ++ct)
                    mma_tf32(acc[rt][ct], a, reinterpret_cast<const uint32_t*>(&bb[cur][ct]));
                if (rt < 1) { a[0] = an[0]; a[1] = an[1]; a[2] = an[2]; a[3] = an[3]; }
            }
        }
        #pragma unroll
        for (int rt = 0; rt < 2; ++rt) {
            #pragma unroll
            for (int ct = 0; ct < 8; ++ct) {
                int r = wr * 32 + rt * 16 + lq;
                int c = wc * 64 + ct * 8 + lr * 2;
                float b0 = __ldg(bn2 + c), b1 = __ldg(bn2 + c + 1);
                int gr = row0 + r;
                if (gr < N_NODES) {
                    float2 xn = *reinterpret_cast<const float2*>(nodes + (size_t)gr * D + c);
                    float2 v  = make_float2(xn.x + acc[rt][ct][0] + b0,
                                            xn.y + acc[rt][ct][1] + b1);
                    *reinterpret_cast<float2*>(out + (size_t)gr * D + c) = v;
                }
                int gr2 = gr + 8;
                if (gr2 < N_NODES) {
                    float2 xn = *reinterpret_cast<const float2*>(nodes + (size_t)gr2 * D + c);
                    float2 v  = make_float2(xn.x + acc[rt][ct][2] + b0,
                                            xn.y + acc[rt][ct][3] + b1);
                    *reinterpret_cast<float2*>(out + (size_t)gr2 * D + c) = v;
                }
            }
        }
    }
}

// ---------------------------------------------------------------------------
// launch
// ---------------------------------------------------------------------------
extern "C" void kernel_launch(void* const* d_in, const int* in_sizes, int n_in,
                              void* d_out, int out_size)
{
    const float* nodes     = (const float*)d_in[0];
    const int*   senders   = (const int*)  d_in[1];
    const int*   receivers = (const int*)  d_in[2];
    const float* Wm1 = (const float*)d_in[3];
    const float* bm1 = (const float*)d_in[4];
    const float* Wm2 = (const float*)d_in[5];
    const float* bm2 = (const float*)d_in[6];
    const float* Wn1 = (const float*)d_in[7];
    const float* bn1 = (const float*)d_in[8];
    const float* Wn2 = (const float*)d_in[9];
    const float* bn2 = (const float*)d_in[10];
    float* out = (float*)d_out;

    const int SMEM1 = (TILE_M * LDX + TILE_M * LDH) * 4;   // 200704 B
    const int SMEM3 = (TILE_M * LDH) * 4;                  // 133120 B
    cudaFuncSetAttribute(msg_mlp_kernel,  cudaFuncAttributeMaxDynamicSharedMemorySize, SMEM1);
    cudaFuncSetAttribute(node_mlp_kernel, cudaFuncAttributeMaxDynamicSharedMemorySize, SMEM3);

    // pack all weights in one launch
    {
        int n = 16*32*32 + 32*16*32 + 32*32*32 + 32*16*32;   // 81920
        pack_all_kernel<<<(n + 255) / 256, 256>>>(Wm1, Wm2, Wn1, Wn2);
    }

    // m = MLP1(nodes); also zeroes g_agg per tile
    msg_mlp_kernel<<<NTILES, 256, SMEM1>>>(nodes, bm1, bm2);

    // agg[recv] += m[send]
    {
        long long threads = (long long)N_EDGES * 32;
        int blocks = (int)((threads + 255) / 256);
        scatter_kernel<<<blocks, 256>>>(senders, receivers);
    }

    // out = nodes + MLP2([nodes||agg])
    node_mlp_kernel<<<NTILES, 256, SMEM3>>>(nodes, bn1, bn2, out);
}

// round 11
// speedup vs baseline: 1.2699x; 1.2699x over previous
#include <cuda_runtime.h>
#include <stdint.h>

#define N_NODES 100000
#define N_EDGES 600000
#define D 128
#define H 256
#define TILE_M 64
#define NTILES ((N_NODES + TILE_M - 1) / TILE_M)   // 1563

#define LDX 132   // smem row stride (floats), 128-col tile
#define LDH 260   // smem row stride (floats), 256-col tile

// Scratch (allocation-free rule: device globals)
__device__ float g_m[(size_t)N_NODES * D];
__device__ float g_agg[(size_t)N_NODES * D];

// Pre-packed tf32 weights in mma-fragment order:
//   pW[(kt*Ng + g)*32 + lane] = { tf32(W[kt*8   + lane%4][g*8 + lane/4]),
//                                 tf32(W[kt*8+4 + lane%4][g*8 + lane/4]) }
__device__ uint2 g_pWm1[16 * 32 * 32];
__device__ uint2 g_pWm2[32 * 16 * 32];
__device__ uint2 g_pWn1[32 * 32 * 32];
__device__ uint2 g_pWn2[32 * 16 * 32];

// ---------------------------------------------------------------------------
// helpers
// ---------------------------------------------------------------------------
__device__ __forceinline__ uint32_t f2tf(float f) {
    uint32_t u;
    asm("cvt.rna.tf32.f32 %0, %1;" : "=r"(u) : "f"(f));
    return u;
}

__device__ __forceinline__ void mma_tf32(float c[4], const uint32_t a[4], const uint32_t* b) {
    asm volatile(
        "mma.sync.aligned.m16n8k8.row.col.f32.tf32.tf32.f32 "
        "{%0,%1,%2,%3}, {%4,%5,%6,%7}, {%8,%9}, {%0,%1,%2,%3};\n"
        : "+f"(c[0]), "+f"(c[1]), "+f"(c[2]), "+f"(c[3])
        : "r"(a[0]), "r"(a[1]), "r"(a[2]), "r"(a[3]),
          "r"(b[0]), "r"(b[1]));
}

// ---------------------------------------------------------------------------
// One fused pack kernel: all four weight matrices -> fragment-ordered tf32
// ---------------------------------------------------------------------------
__device__ __forceinline__ void pack_one(const float* __restrict__ W,
                                         uint2* __restrict__ pW,
                                         int id, int Ng, int N)
{
    int lane = id & 31;
    int g    = (id >> 5) % Ng;
    int kt   = (id >> 5) / Ng;
    int lr = lane & 3, lq = lane >> 2;
    int col = g * 8 + lq;
    uint2 v;
    v.x = f2tf(W[(size_t)(kt * 8 + lr)     * N + col]);
    v.y = f2tf(W[(size_t)(kt * 8 + 4 + lr) * N + col]);
    pW[id] = v;
}

__global__ void pack_all_kernel(const float* __restrict__ Wm1, const float* __restrict__ Wm2,
                                const float* __restrict__ Wn1, const float* __restrict__ Wn2)
{
    const int n1 = 16 * 32 * 32;
    const int n2 = 32 * 16 * 32;
    const int n3 = 32 * 32 * 32;
    const int n4 = 32 * 16 * 32;
    int id = blockIdx.x * 256 + threadIdx.x;
    if (id < n1)                     pack_one(Wm1, g_pWm1, id,                32, H);
    else if (id < n1 + n2)           pack_one(Wm2, g_pWm2, id - n1,           16, D);
    else if (id < n1 + n2 + n3)      pack_one(Wn1, g_pWn1, id - n1 - n2,      32, H);
    else if (id < n1 + n2 + n3 + n4) pack_one(Wn2, g_pWn2, id - n1 - n2 - n3, 16, D);
}

// ---------------------------------------------------------------------------
// Kernel 1: m = relu(X @ Wm1 + bm1) @ Wm2 + bm2   + zero g_agg rows
//   64-row tiles, 256 threads (8 warps), 2 CTAs/SM.
//   GEMM1: warp w owns all 64 rows x cols [w*32, w*32+32)  (rt=4, ct=4)
//   GEMM2: warp grid 2x4, warp tile 32x32                  (rt=2, ct=4)
// ---------------------------------------------------------------------------
__global__ __launch_bounds__(256, 2)
void msg_mlp_kernel(const float* __restrict__ nodes,
                    const float* __restrict__ bm1, const float* __restrict__ bm2)
{
    extern __shared__ uint32_t smem[];
    uint32_t* sX = smem;                    // [64][LDX]
    uint32_t* sH = smem + TILE_M * LDX;     // [64][LDH]

    const int row0 = blockIdx.x * TILE_M;
    const int tid  = threadIdx.x;
    const int warp = tid >> 5;
    const int lane = tid & 31;
    const int lq   = lane >> 2;
    const int lr   = lane & 3;

    // zero this tile's g_agg rows
    for (int i = tid; i < TILE_M * (D / 4); i += 256) {
        int r  = i >> 5;
        int c4 = (i & 31) * 4;
        int gr = row0 + r;
        if (gr < N_NODES)
            *reinterpret_cast<float4*>(g_agg + (size_t)gr * D + c4) =
                make_float4(0.f, 0.f, 0.f, 0.f);
    }

    // stage X tile (fp32 -> tf32)
    for (int i = tid; i < TILE_M * (D / 4); i += 256) {
        int r  = i >> 5;
        int c4 = (i & 31) * 4;
        float4 v = make_float4(0.f, 0.f, 0.f, 0.f);
        int gr = row0 + r;
        if (gr < N_NODES) v = *reinterpret_cast<const float4*>(nodes + (size_t)gr * D + c4);
        uint32_t* dst = sX + r * LDX + c4;
        dst[0] = f2tf(v.x); dst[1] = f2tf(v.y); dst[2] = f2tf(v.z); dst[3] = f2tf(v.w);
    }
    __syncthreads();

    // ---- GEMM1: hidden[64x256] = relu(X @ Wm1 + bm1)
    {
        const int g0 = warp * 4;            // cols warp*32
        const int KT = D / 8;               // 16
        const int NG = H / 8;               // 32

        float acc[4][4][4];
        #pragma unroll
        for (int i = 0; i < 4; ++i)
            #pragma unroll
            for (int j = 0; j < 4; ++j)
                #pragma unroll
                for (int k = 0; k < 4; ++k) acc[i][j][k] = 0.f;

        uint2 bb[2][4];
        #pragma unroll
        for (int ct = 0; ct < 4; ++ct)
            bb[0][ct] = g_pWm1[(size_t)(g0 + ct) * 32 + lane];

        #pragma unroll 1
        for (int kt = 0; kt < KT; ++kt) {
            const int cur = kt & 1;
            if (kt + 1 < KT) {
                #pragma unroll
                for (int ct = 0; ct < 4; ++ct)
                    bb[cur ^ 1][ct] = g_pWm1[(size_t)((kt + 1) * NG + g0 + ct) * 32 + lane];
            }
            const int kb = kt * 8;
            #pragma unroll
            for (int rt = 0; rt < 4; ++rt) {
                const uint32_t* base = sX + (rt * 16 + lq) * LDX + kb + lr;
                uint32_t a[4];
                a[0] = base[0];
                a[1] = base[8 * LDX];
                a[2] = base[4];
                a[3] = base[8 * LDX + 4];
                #pragma unroll
                for (int ct = 0; ct < 4; ++ct)
                    mma_tf32(acc[rt][ct], a, reinterpret_cast<const uint32_t*>(&bb[cur][ct]));
            }
        }
        // bias + relu -> sH (tf32)
        #pragma unroll
        for (int rt = 0; rt < 4; ++rt) {
            #pragma unroll
            for (int ct = 0; ct < 4; ++ct) {
                int r = rt * 16 + lq;
                int c = warp * 32 + ct * 8 + lr * 2;
                float b0 = __ldg(bm1 + c), b1 = __ldg(bm1 + c + 1);
                sH[r * LDH + c]           = f2tf(fmaxf(acc[rt][ct][0] + b0, 0.f));
                sH[r * LDH + c + 1]       = f2tf(fmaxf(acc[rt][ct][1] + b1, 0.f));
                sH[(r + 8) * LDH + c]     = f2tf(fmaxf(acc[rt][ct][2] + b0, 0.f));
                sH[(r + 8) * LDH + c + 1] = f2tf(fmaxf(acc[rt][ct][3] + b1, 0.f));
            }
        }
    }
    __syncthreads();

    // ---- GEMM2: m[64x128] = hidden @ Wm2 + bm2
    {
        const int wr = warp >> 2;           // 0..1 -> rows wr*32
        const int wc = warp & 3;            // 0..3 -> cols wc*32
        const int g0 = wc * 4;
        const int KT = H / 8;               // 32
        const int NG = D / 8;               // 16

        float acc[2][4][4];
        #pragma unroll
        for (int i = 0; i < 2; ++i)
            #pragma unroll
            for (int j = 0; j < 4; ++j)
                #pragma unroll
                for (int k = 0; k < 4; ++k) acc[i][j][k] = 0.f;

        uint2 bb[2][4];
        #pragma unroll
        for (int ct = 0; ct < 4; ++ct)
            bb[0][ct] = g_pWm2[(size_t)(g0 + ct) * 32 + lane];

        #pragma unroll 1
        for (int kt = 0; kt < KT; ++kt) {
            const int cur = kt & 1;
            if (kt + 1 < KT) {
                #pragma unroll
                for (int ct = 0; ct < 4; ++ct)
                    bb[cur ^ 1][ct] = g_pWm2[(size_t)((kt + 1) * NG + g0 + ct) * 32 + lane];
            }
            const int kb = kt * 8;
            #pragma unroll
            for (int rt = 0; rt < 2; ++rt) {
                const uint32_t* base = sH + (wr * 32 + rt * 16 + lq) * LDH + kb + lr;
                uint32_t a[4];
                a[0] = base[0];
                a[1] = base[8 * LDH];
                a[2] = base[4];
                a[3] = base[8 * LDH + 4];
                #pragma unroll
                for (int ct = 0; ct < 4; ++ct)
                    mma_tf32(acc[rt][ct], a, reinterpret_cast<const uint32_t*>(&bb[cur][ct]));
            }
        }
        #pragma unroll
        for (int rt = 0; rt < 2; ++rt) {
            #pragma unroll
            for (int ct = 0; ct < 4; ++ct) {
                int r = wr * 32 + rt * 16 + lq;
                int c = wc * 32 + ct * 8 + lr * 2;
                float b0 = __ldg(bm2 + c), b1 = __ldg(bm2 + c + 1);
                int gr = row0 + r;
                if (gr < N_NODES) {
                    float2 v = make_float2(acc[rt][ct][0] + b0, acc[rt][ct][1] + b1);
                    *reinterpret_cast<float2*>(g_m + (size_t)gr * D + c) = v;
                }
                int gr2 = gr + 8;
                if (gr2 < N_NODES) {
                    float2 v = make_float2(acc[rt][ct][2] + b0, acc[rt][ct][3] + b1);
                    *reinterpret_cast<float2*>(g_m + (size_t)gr2 * D + c) = v;
                }
            }
        }
    }
}

// ---------------------------------------------------------------------------
// Kernel 2: agg[recv] += m[send]   (one warp per edge, vector red to L2)
// ---------------------------------------------------------------------------
__global__ __launch_bounds__(256)
void scatter_kernel(const int* __restrict__ senders, const int* __restrict__ receivers)
{
    int e = (blockIdx.x * 256 + threadIdx.x) >> 5;
    int lane = threadIdx.x & 31;
    if (e >= N_EDGES) return;
    int s = __ldg(senders + e);
    int r = __ldg(receivers + e);
    float4 v = *reinterpret_cast<const float4*>(g_m + (size_t)s * D + lane * 4);
    float* dst = g_agg + (size_t)r * D + lane * 4;
    asm volatile("red.global.add.v4.f32 [%0], {%1,%2,%3,%4};"
                 :: "l"(dst), "f"(v.x), "f"(v.y), "f"(v.z), "f"(v.w)
                 : "memory");
}

// ---------------------------------------------------------------------------
// Kernel 3: out = nodes + relu([nodes||agg] @ Wn1 + bn1) @ Wn2 + bn2
//   64-row tiles, 256 threads, 2 CTAs/SM.
// ---------------------------------------------------------------------------
__global__ __launch_bounds__(256, 2)
void node_mlp_kernel(const float* __restrict__ nodes,
                     const float* __restrict__ bn1, const float* __restrict__ bn2,
                     float* __restrict__ out)
{
    extern __shared__ uint32_t smem[];
    uint32_t* sA = smem;   // [64][LDH]; A = [X||agg], later reused as hidden

    const int row0 = blockIdx.x * TILE_M;
    const int tid  = threadIdx.x;
    const int warp = tid >> 5;
    const int lane = tid & 31;
    const int lq   = lane >> 2;
    const int lr   = lane & 3;

    // stage A = [nodes || agg], 64 x 256, tf32
    for (int i = tid; i < TILE_M * (2 * D / 4); i += 256) {
        int r  = i >> 6;
        int c4 = (i & 63) * 4;
        float4 v = make_float4(0.f, 0.f, 0.f, 0.f);
        int gr = row0 + r;
        if (gr < N_NODES) {
            if (c4 < D) v = *reinterpret_cast<const float4*>(nodes + (size_t)gr * D + c4);
            else        v = *reinterpret_cast<const float4*>(g_agg + (size_t)gr * D + (c4 - D));
        }
        uint32_t* dst = sA + r * LDH + c4;
        dst[0] = f2tf(v.x); dst[1] = f2tf(v.y); dst[2] = f2tf(v.z); dst[3] = f2tf(v.w);
    }
    __syncthreads();

    // ---- GEMM1: hidden[64x256] = relu(A @ Wn1 + bn1); warp owns 32 cols
    float acc1[4][4][4];
    #pragma unroll
    for (int i = 0; i < 4; ++i)
        #pragma unroll
        for (int j = 0; j < 4; ++j)
            #pragma unroll
            for (int k = 0; k < 4; ++k) acc1[i][j][k] = 0.f;

    {
        const int g0 = warp * 4;
        const int KT = (2 * D) / 8;         // 32
        const int NG = H / 8;               // 32

        uint2 bb[2][4];
        #pragma unroll
        for (int ct = 0; ct < 4; ++ct)
            bb[0][ct] = g_pWn1[(size_t)(g0 + ct) * 32 + lane];

        #pragma unroll 1
        for (int kt = 0; kt < KT; ++kt) {
            const int cur = kt & 1;
            if (kt + 1 < KT) {
                #pragma unroll
                for (int ct = 0; ct < 4; ++ct)
                    bb[cur ^ 1][ct] = g_pWn1[(size_t)((kt + 1) * NG + g0 + ct) * 32 + lane];
            }
            const int kb = kt * 8;
            #pragma unroll
            for (int rt = 0; rt < 4; ++rt) {
                const uint32_t* base = sA + (rt * 16 + lq) * LDH + kb + lr;
                uint32_t a[4];
                a[0] = base[0];
                a[1] = base[8 * LDH];
                a[2] = base[4];
                a[3] = base[8 * LDH + 4];
                #pragma unroll
                for (int ct = 0; ct < 4; ++ct)
                    mma_tf32(acc1[rt][ct], a, reinterpret_cast<const uint32_t*>(&bb[cur][ct]));
            }
        }
    }
    __syncthreads();   // all warps done READING sA

    // write hidden (bias + relu, tf32) over sA
    #pragma unroll
    for (int rt = 0; rt < 4; ++rt) {
        #pragma unroll
        for (int ct = 0; ct < 4; ++ct) {
            int r = rt * 16 + lq;
            int c = warp * 32 + ct * 8 + lr * 2;
            float b0 = __ldg(bn1 + c), b1 = __ldg(bn1 + c + 1);
            sA[r * LDH + c]           = f2tf(fmaxf(acc1[rt][ct][0] + b0, 0.f));
            sA[r * LDH + c + 1]       = f2tf(fmaxf(acc1[rt][ct][1] + b1, 0.f));
            sA[(r + 8) * LDH + c]     = f2tf(fmaxf(acc1[rt][ct][2] + b0, 0.f));
            sA[(r + 8) * LDH + c + 1] = f2tf(fmaxf(acc1[rt][ct][3] + b1, 0.f));
        }
    }
    __syncthreads();

    // ---- GEMM2: out = nodes + hidden @ Wn2 + bn2
    {
        const int wr = warp >> 2;           // 0..1
        const int wc = warp & 3;            // 0..3
        const int g0 = wc * 4;
        const int KT = H / 8;               // 32
        const int NG = D / 8;               // 16

        float acc[2][4][4];
        #pragma unroll
        for (int i = 0; i < 2; ++i)
            #pragma unroll
            for (int j = 0; j < 4; ++j)
                #pragma unroll
                for (int k = 0; k < 4; ++k) acc[i][j][k] = 0.f;

        uint2 bb[2][4];
        #pragma unroll
        for (int ct = 0; ct < 4; ++ct)
            bb[0][ct] = g_pWn2[(size_t)(g0 + ct) * 32 + lane];

        #pragma unroll 1
        for (int kt = 0; kt < KT; ++kt) {
            const int cur = kt & 1;
            if (kt + 1 < KT) {
                #pragma unroll
                for (int ct = 0; ct < 4; ++ct)
                    bb[cur ^ 1][ct] = g_pWn2[(size_t)((kt + 1) * NG + g0 + ct) * 32 + lane];
            }
            const int kb = kt * 8;
            #pragma unroll
            for (int rt = 0; rt < 2; ++rt) {
                const uint32_t* base = sA + (wr * 32 + rt * 16 + lq) * LDH + kb + lr;
                uint32_t a[4];
                a[0] = base[0];
                a[1] = base[8 * LDH];
                a[2] = base[4];
                a[3] = base[8 * LDH + 4];
                #pragma unroll
                for (int ct = 0; ct < 4; ++ct)
                    mma_tf32(acc[rt][ct], a, reinterpret_cast<const uint32_t*>(&bb[cur][ct]));
            }
        }
        #pragma unroll
        for (int rt = 0; rt < 2; ++rt) {
            #pragma unroll
            for (int ct = 0; ct < 4; ++ct) {
                int r = wr * 32 + rt * 16 + lq;
                int c = wc * 32 + ct * 8 + lr * 2;
                float b0 = __ldg(bn2 + c), b1 = __ldg(bn2 + c + 1);
                int gr = row0 + r;
                if (gr < N_NODES) {
                    float2 xn = *reinterpret_cast<const float2*>(nodes + (size_t)gr * D + c);
                    float2 v  = make_float2(xn.x + acc[rt][ct][0] + b0,
                                            xn.y + acc[rt][ct][1] + b1);
                    *reinterpret_cast<float2*>(out + (size_t)gr * D + c) = v;
                }
                int gr2 = gr + 8;
                if (gr2 < N_NODES) {
                    float2 xn = *reinterpret_cast<const float2*>(nodes + (size_t)gr2 * D + c);
                    float2 v  = make_float2(xn.x + acc[rt][ct][2] + b0,
                                            xn.y + acc[rt][ct][3] + b1);
                    *reinterpret_cast<float2*>(out + (size_t)gr2 * D + c) = v;
                }
            }
        }
    }
}

// ---------------------------------------------------------------------------
// launch
// ---------------------------------------------------------------------------
extern "C" void kernel_launch(void* const* d_in, const int* in_sizes, int n_in,
                              void* d_out, int out_size)
{
    const float* nodes     = (const float*)d_in[0];
    const int*   senders   = (const int*)  d_in[1];
    const int*   receivers = (const int*)  d_in[2];
    const float* Wm1 = (const float*)d_in[3];
    const float* bm1 = (const float*)d_in[4];
    const float* Wm2 = (const float*)d_in[5];
    const float* bm2 = (const float*)d_in[6];
    const float* Wn1 = (const float*)d_in[7];
    const float* bn1 = (const float*)d_in[8];
    const float* Wn2 = (const float*)d_in[9];
    const float* bn2 = (const float*)d_in[10];
    float* out = (float*)d_out;

    const int SMEM1 = (TILE_M * LDX + TILE_M * LDH) * 4;   // 100352 B -> 2 CTA/SM
    const int SMEM3 = (TILE_M * LDH) * 4;                  // 66560 B  -> 2 CTA/SM
    cudaFuncSetAttribute(msg_mlp_kernel,  cudaFuncAttributeMaxDynamicSharedMemorySize, SMEM1);
    cudaFuncSetAttribute(node_mlp_kernel, cudaFuncAttributeMaxDynamicSharedMemorySize, SMEM3);

    // pack all weights in one launch
    {
        int n = 16*32*32 + 32*16*32 + 32*32*32 + 32*16*32;   // 81920
        pack_all_kernel<<<(n + 255) / 256, 256>>>(Wm1, Wm2, Wn1, Wn2);
    }

    // m = MLP1(nodes); also zeroes g_agg per tile
    msg_mlp_kernel<<<NTILES, 256, SMEM1>>>(nodes, bm1, bm2);

    // agg[recv] += m[send]
    {
        long long threads = (long long)N_EDGES * 32;
        int blocks = (int)((threads + 255) / 256);
        scatter_kernel<<<blocks, 256>>>(senders, receivers);
    }

    // out = nodes + MLP2([nodes||agg])
    node_mlp_kernel<<<NTILES, 256, SMEM3>>>(nodes, bn1, bn2, out);
}